// round 1
// baseline (speedup 1.0000x reference)
#include <cuda_runtime.h>
#include <math.h>

// ---------------- problem constants ----------------
#define EDIM 1024
#define NH   16
#define HD   64          // head dim (DK == DV)
#define TLEN 2048
#define SLEN 2048
#define BSZ  2
#define NZ   (BSZ*NH)    // 32 heads total
#define MTOK (TLEN*BSZ)  // 4096 tokens
#define SCALING 0.125f   // 64^-0.5
#define DTHRESH 3.8918202981106265f   // log(2000/40 - 1) = log(49)

#define ATTN_ELEMS ((size_t)TLEN*BSZ*EDIM)   //   4,194,304
#define WEIGHT_ELEMS ((size_t)NZ*TLEN*SLEN)  // 134,217,728

// ---------------- scratch (device globals: no allocation allowed) ----------------
static __device__ float g_Q[(size_t)TLEN*BSZ*EDIM];   // 16 MB
static __device__ float g_K[(size_t)SLEN*BSZ*EDIM];   // 16 MB
static __device__ float g_V[(size_t)SLEN*BSZ*EDIM];   // 16 MB
static __device__ float g_S[(size_t)NZ*TLEN*SLEN];    // 512 MB raw scores (and probs if not exported)
static __device__ float g_A[(size_t)TLEN*BSZ*EDIM];   // 16 MB attn before out-projection

// ============================================================================
// Generic NT GEMM:  Y[M,N] = (X[M,K] @ W[N,K]^T + bias[N]) * scale
// BM=BN=64, BK=16, 256 threads, 4x4 micro-tile per thread.
// ============================================================================
__global__ __launch_bounds__(256)
void gemm_nt(const float* __restrict__ X, const float* __restrict__ W,
             const float* __restrict__ bias, float* __restrict__ Y,
             int M, int N, int K, float scale)
{
    __shared__ float Xs[16][68];   // [k][m], pad 68 keeps float4 reads 16B-aligned
    __shared__ float Ws[16][68];   // [k][n]

    const int tid = threadIdx.x;
    const int tx = tid & 15;
    const int ty = tid >> 4;
    const int m0 = blockIdx.y * 64;
    const int n0 = blockIdx.x * 64;

    float acc[4][4] = {};

    const int lr = tid >> 2;          // 0..63 (row within tile)
    const int lc = (tid & 3) * 4;     // 0,4,8,12 (k offset)

    for (int k0 = 0; k0 < K; k0 += 16) {
        float4 xv = *(const float4*)(X + (size_t)(m0 + lr) * K + k0 + lc);
        Xs[lc+0][lr] = xv.x; Xs[lc+1][lr] = xv.y; Xs[lc+2][lr] = xv.z; Xs[lc+3][lr] = xv.w;
        float4 wv = *(const float4*)(W + (size_t)(n0 + lr) * K + k0 + lc);
        Ws[lc+0][lr] = wv.x; Ws[lc+1][lr] = wv.y; Ws[lc+2][lr] = wv.z; Ws[lc+3][lr] = wv.w;
        __syncthreads();

        #pragma unroll
        for (int kk = 0; kk < 16; kk++) {
            float4 a = *(const float4*)&Xs[kk][ty*4];
            float4 w = *(const float4*)&Ws[kk][tx*4];
            acc[0][0] += a.x*w.x; acc[0][1] += a.x*w.y; acc[0][2] += a.x*w.z; acc[0][3] += a.x*w.w;
            acc[1][0] += a.y*w.x; acc[1][1] += a.y*w.y; acc[1][2] += a.y*w.z; acc[1][3] += a.y*w.w;
            acc[2][0] += a.z*w.x; acc[2][1] += a.z*w.y; acc[2][2] += a.z*w.z; acc[2][3] += a.z*w.w;
            acc[3][0] += a.w*w.x; acc[3][1] += a.w*w.y; acc[3][2] += a.w*w.z; acc[3][3] += a.w*w.w;
        }
        __syncthreads();
    }

    float4 bv = *(const float4*)(bias + n0 + tx*4);
    #pragma unroll
    for (int i = 0; i < 4; i++) {
        float4 r;
        r.x = (acc[i][0] + bv.x) * scale;
        r.y = (acc[i][1] + bv.y) * scale;
        r.z = (acc[i][2] + bv.z) * scale;
        r.w = (acc[i][3] + bv.w) * scale;
        *(float4*)(Y + (size_t)(m0 + ty*4 + i) * N + n0 + tx*4) = r;
    }
}

// ============================================================================
// QK^T: scores[z, t, s] = sum_d Q[t, b, h*64+d] * K[s, b, h*64+d]
// One block per (z, 64x64 output tile). Full K=64 in smem.
// ============================================================================
__global__ __launch_bounds__(256)
void qk_kernel(const float* __restrict__ Q, const float* __restrict__ K,
               float* __restrict__ Sout)
{
    const int z = blockIdx.z;
    const int b = z / NH, h = z % NH;
    const int t0 = blockIdx.y * 64;
    const int s0 = blockIdx.x * 64;

    __shared__ float Qs[64][68];   // [k][t]
    __shared__ float Ks[64][68];   // [k][s]

    const int tid = threadIdx.x;
    const int tx = tid & 15;
    const int ty = tid >> 4;

    // load 64x64 fp32 Q and K tiles (transposed into [k][row])
    {
        const int r = tid >> 2;
        const int cb = (tid & 3) * 4;
        #pragma unroll
        for (int u = 0; u < 4; u++) {
            const int c = cb + u * 16;
            float4 qv = *(const float4*)(Q + ((size_t)(t0 + r) * BSZ + b) * EDIM + h * HD + c);
            Qs[c+0][r] = qv.x; Qs[c+1][r] = qv.y; Qs[c+2][r] = qv.z; Qs[c+3][r] = qv.w;
            float4 kv = *(const float4*)(K + ((size_t)(s0 + r) * BSZ + b) * EDIM + h * HD + c);
            Ks[c+0][r] = kv.x; Ks[c+1][r] = kv.y; Ks[c+2][r] = kv.z; Ks[c+3][r] = kv.w;
        }
    }
    __syncthreads();

    float acc[4][4] = {};
    #pragma unroll 16
    for (int kk = 0; kk < 64; kk++) {
        float4 a = *(const float4*)&Qs[kk][ty*4];
        float4 w = *(const float4*)&Ks[kk][tx*4];
        acc[0][0] += a.x*w.x; acc[0][1] += a.x*w.y; acc[0][2] += a.x*w.z; acc[0][3] += a.x*w.w;
        acc[1][0] += a.y*w.x; acc[1][1] += a.y*w.y; acc[1][2] += a.y*w.z; acc[1][3] += a.y*w.w;
        acc[2][0] += a.z*w.x; acc[2][1] += a.z*w.y; acc[2][2] += a.z*w.z; acc[2][3] += a.z*w.w;
        acc[3][0] += a.w*w.x; acc[3][1] += a.w*w.y; acc[3][2] += a.w*w.z; acc[3][3] += a.w*w.w;
    }

    #pragma unroll
    for (int i = 0; i < 4; i++) {
        float4 r = make_float4(acc[i][0], acc[i][1], acc[i][2], acc[i][3]);
        *(float4*)(Sout + ((size_t)z * TLEN + t0 + ty*4 + i) * SLEN + s0 + tx*4) = r;
    }
}

// ============================================================================
// Row softmax with mask + dynamic threshold drop.
// One block (256 thr) per (z,t) row of 2048; row held in registers (8/thread).
// ============================================================================
__global__ __launch_bounds__(256)
void softmax_kernel(const float* __restrict__ Sin, const int* __restrict__ mask,
                    float* __restrict__ P)
{
    const int row = blockIdx.x;          // z*TLEN + t
    const int t = row & (TLEN - 1);
    const int tid = threadIdx.x;
    const float* sr = Sin + (size_t)row * SLEN;

    float v[8];
    float m = -INFINITY;
    #pragma unroll
    for (int i = 0; i < 8; i++) {
        const int s = tid + i * 256;
        float x = sr[s];
        if (mask[(size_t)t * SLEN + s] == 0) x = -INFINITY;
        v[i] = x;
        m = fmaxf(m, x);
    }

    __shared__ float red[256];
    red[tid] = m;
    __syncthreads();
    #pragma unroll
    for (int st = 128; st > 0; st >>= 1) {
        if (tid < st) red[tid] = fmaxf(red[tid], red[tid + st]);
        __syncthreads();
    }
    m = red[0];
    __syncthreads();

    const float thr = m - DTHRESH;
    float sum = 0.f;
    #pragma unroll
    for (int i = 0; i < 8; i++) {
        float e = (v[i] < thr) ? 0.0f : __expf(v[i] - m);
        v[i] = e;
        sum += e;
    }
    red[tid] = sum;
    __syncthreads();
    #pragma unroll
    for (int st = 128; st > 0; st >>= 1) {
        if (tid < st) red[tid] += red[tid + st];
        __syncthreads();
    }
    const float inv = 1.0f / red[0];

    float* pr = P + (size_t)row * SLEN;
    #pragma unroll
    for (int i = 0; i < 8; i++)
        pr[tid + i * 256] = v[i] * inv;
}

// ============================================================================
// PV: attn[z, t, d] = sum_s P[z,t,s] * V[s, b, h*64+d]
// One block per (z, 64-row t tile). BK=32 over S. Writes [T,B,E] layout.
// ============================================================================
__global__ __launch_bounds__(256)
void pv_kernel(const float* __restrict__ P, const float* __restrict__ V,
               float* __restrict__ A)
{
    const int z = blockIdx.y;
    const int b = z / NH, h = z % NH;
    const int t0 = blockIdx.x * 64;

    __shared__ float Ps[32][68];   // [s][t]
    __shared__ float Vs[32][68];   // [s][d]

    const int tid = threadIdx.x;
    const int tx = tid & 15;
    const int ty = tid >> 4;

    float acc[4][4] = {};

    for (int s0 = 0; s0 < SLEN; s0 += 32) {
        // P tile: 64 t-rows x 32 s, transposed into [s][t]
        {
            const int r = tid >> 2;             // t row 0..63
            const int cb = (tid & 3) * 8;       // s offset 0,8,16,24
            #pragma unroll
            for (int u = 0; u < 8; u += 4) {
                float4 pv = *(const float4*)(P + ((size_t)z * TLEN + t0 + r) * SLEN + s0 + cb + u);
                Ps[cb+u+0][r] = pv.x; Ps[cb+u+1][r] = pv.y; Ps[cb+u+2][r] = pv.z; Ps[cb+u+3][r] = pv.w;
            }
        }
        // V tile: 32 s-rows x 64 d, natural layout
        {
            const int r = tid >> 3;             // s row 0..31
            const int c = (tid & 7) * 8;        // d offset
            const float* vp = V + ((size_t)(s0 + r) * BSZ + b) * EDIM + h * HD + c;
            *(float4*)&Vs[r][c]     = *(const float4*)(vp);
            *(float4*)&Vs[r][c + 4] = *(const float4*)(vp + 4);
        }
        __syncthreads();

        #pragma unroll
        for (int kk = 0; kk < 32; kk++) {
            float4 a = *(const float4*)&Ps[kk][ty*4];
            float4 w = *(const float4*)&Vs[kk][tx*4];
            acc[0][0] += a.x*w.x; acc[0][1] += a.x*w.y; acc[0][2] += a.x*w.z; acc[0][3] += a.x*w.w;
            acc[1][0] += a.y*w.x; acc[1][1] += a.y*w.y; acc[1][2] += a.y*w.z; acc[1][3] += a.y*w.w;
            acc[2][0] += a.z*w.x; acc[2][1] += a.z*w.y; acc[2][2] += a.z*w.z; acc[2][3] += a.z*w.w;
            acc[3][0] += a.w*w.x; acc[3][1] += a.w*w.y; acc[3][2] += a.w*w.z; acc[3][3] += a.w*w.w;
        }
        __syncthreads();
    }

    #pragma unroll
    for (int i = 0; i < 4; i++) {
        float4 r = make_float4(acc[i][0], acc[i][1], acc[i][2], acc[i][3]);
        *(float4*)(A + ((size_t)(t0 + ty*4 + i) * BSZ + b) * EDIM + h * HD + tx*4) = r;
    }
}

// ============================================================================
// Launch
// ============================================================================
extern "C" void kernel_launch(void* const* d_in, const int* in_sizes, int n_in,
                              void* d_out, int out_size)
{
    const float* query = (const float*)d_in[0];
    const float* key   = (const float*)d_in[1];
    const float* value = (const float*)d_in[2];
    const int*   mask  = (const int*)  d_in[3];
    const float* Wq    = (const float*)d_in[4];
    const float* bq    = (const float*)d_in[5];
    const float* Wk    = (const float*)d_in[6];
    const float* bk    = (const float*)d_in[7];
    const float* Wv    = (const float*)d_in[8];
    const float* bv    = (const float*)d_in[9];
    const float* Wo    = (const float*)d_in[10];
    const float* bo    = (const float*)d_in[11];
    float* out = (float*)d_out;

    float *pQ, *pK, *pV, *pS, *pA;
    cudaGetSymbolAddress((void**)&pQ, g_Q);
    cudaGetSymbolAddress((void**)&pK, g_K);
    cudaGetSymbolAddress((void**)&pV, g_V);
    cudaGetSymbolAddress((void**)&pS, g_S);
    cudaGetSymbolAddress((void**)&pA, g_A);

    // If the harness exports the (attn, attn_weights) tuple, the weights live
    // right after attn in d_out; otherwise keep them in scratch (in-place).
    const bool export_weights = ((size_t)out_size >= ATTN_ELEMS + WEIGHT_ELEMS);
    float* weights = export_weights ? (out + ATTN_ELEMS) : pS;

    dim3 gproj(EDIM / 64, MTOK / 64);          // 16 x 64
    gemm_nt<<<gproj, 256>>>(query, Wq, bq, pQ, MTOK, EDIM, EDIM, SCALING);
    gemm_nt<<<gproj, 256>>>(key,   Wk, bk, pK, MTOK, EDIM, EDIM, 1.0f);
    gemm_nt<<<gproj, 256>>>(value, Wv, bv, pV, MTOK, EDIM, EDIM, 1.0f);

    dim3 gqk(SLEN / 64, TLEN / 64, NZ);        // 32 x 32 x 32
    qk_kernel<<<gqk, 256>>>(pQ, pK, pS);

    softmax_kernel<<<NZ * TLEN, 256>>>(pS, mask, weights);

    dim3 gpv(TLEN / 64, NZ);                   // 32 x 32
    pv_kernel<<<gpv, 256>>>(weights, pV, pA);

    gemm_nt<<<gproj, 256>>>(pA, Wo, bo, out, MTOK, EDIM, EDIM, 1.0f);
}

// round 6
// speedup vs baseline: 1.7833x; 1.7833x over previous
#include <cuda_runtime.h>
#include <cuda_bf16.h>
#include <math.h>
#include <cstdint>

// ---------------- problem constants ----------------
#define EDIM 1024
#define NH   16
#define HD   64
#define TLEN 2048
#define SLEN 2048
#define BSZ  2
#define NZ   (BSZ*NH)    // 32
#define MTOK (TLEN*BSZ)  // 4096
#define SCALING 0.125f
#define DTHRESH 3.8918202981106265f

#define ATTN_ELEMS ((size_t)TLEN*BSZ*EDIM)
#define WEIGHT_ELEMS ((size_t)NZ*TLEN*SLEN)

// ---------------- scratch ----------------
static __device__ float g_Q[(size_t)NZ*TLEN*HD];      // [z][t][64]
static __device__ float g_K[(size_t)NZ*SLEN*HD];      // [z][s][64]
static __device__ float g_Vt[(size_t)NZ*HD*SLEN];     // [z][64][s]
static __device__ float g_S[(size_t)NZ*TLEN*SLEN];    // scores / probs
static __device__ float g_A[(size_t)MTOK*EDIM];       // attn pre-out-proj [token][f]

// ---------------- tile config ----------------
#define BM 128
#define BN 64
#define BK 32
#define ROWB 80            // smem row stride bytes (32 bf16 = 64B data + 16 pad)

// smem layout (bytes)
#define SM_AH 0                        // 128*80 = 10240
#define SM_AL 10240                    // 10240
#define SM_BH 20480                    // 64*80 = 5120
#define SM_BL 25600                    // 5120  -> 30720
#define SM_STAGE 0                     // reused after mainloop: 128*68*4 = 34816
#define SM_BIAS 34816                  // 64 floats
#define SMEM_BYTES (34816 + 256)
#define STG_LD 68                      // stage row stride (floats)

__device__ __forceinline__ uint32_t smem_u32(const void* p) {
    uint32_t a;
    asm("{ .reg .u64 t; cvta.to.shared.u64 t, %1; cvt.u32.u64 %0, t; }" : "=r"(a) : "l"(p));
    return a;
}

__device__ __forceinline__ uint4 ldm_x4(uint32_t addr) {
    uint4 r;
    asm volatile("ldmatrix.sync.aligned.m8n8.x4.shared.b16 {%0,%1,%2,%3}, [%4];"
                 : "=r"(r.x), "=r"(r.y), "=r"(r.z), "=r"(r.w) : "r"(addr));
    return r;
}

// D += A(16x16) * B(16x8), bf16 inputs, fp32 accum
__device__ __forceinline__ void mma16816(float* d, const uint4& a, uint32_t b0, uint32_t b1) {
    asm volatile("mma.sync.aligned.m16n8k16.row.col.f32.bf16.bf16.f32 "
                 "{%0,%1,%2,%3}, {%4,%5,%6,%7}, {%8,%9}, {%0,%1,%2,%3};"
                 : "+f"(d[0]), "+f"(d[1]), "+f"(d[2]), "+f"(d[3])
                 : "r"(a.x), "r"(a.y), "r"(a.z), "r"(a.w), "r"(b0), "r"(b1));
}

// split float -> (hi, lo) bf16; pack two lanes into u32
__device__ __forceinline__ void split2(float x, float y, uint32_t& hi, uint32_t& lo) {
    __nv_bfloat16 hx = __float2bfloat16(x);
    __nv_bfloat16 hy = __float2bfloat16(y);
    __nv_bfloat16 lx = __float2bfloat16(x - __bfloat162float(hx));
    __nv_bfloat16 ly = __float2bfloat16(y - __bfloat162float(hy));
    hi = (uint32_t)__bfloat16_as_ushort(hx) | ((uint32_t)__bfloat16_as_ushort(hy) << 16);
    lo = (uint32_t)__bfloat16_as_ushort(lx) | ((uint32_t)__bfloat16_as_ushort(ly) << 16);
}

// ============================================================================
// Unified GEMM:  C[BMxBN] = A[BM x K] * B[BN x K]^T   (both K-contiguous)
// MODE 0: proj -> plain [token][1024]
// MODE 1: proj -> per-head q/k  [z][t][64]
// MODE 2: proj -> Vt            [z][64][s]
// MODE 3: QK   -> scores        [z][t][s]
// MODE 4: PV   -> attn          [token][1024] (n0 = 0, N=64 per z)
// bf16 2-way split, 3 mma products per logical mma (AhBh + AhBl + AlBh).
// ============================================================================
template <int MODE>
__global__ __launch_bounds__(256, 2)
void mma_gemm(const float* __restrict__ Abase, const float* __restrict__ Bbase,
              const float* __restrict__ bias, float* __restrict__ out,
              float scale, int lda, int ldb, int Ktot)
{
    extern __shared__ char sm[];
    const uint32_t smb = smem_u32(sm);
    const int tid = threadIdx.x;
    const int lane = tid & 31, wid = tid >> 5;
    const int wm = (wid & 3) * 32;          // warp M offset (4 warps over 128)
    const int wn = (wid >> 2) * 32;         // warp N offset (2 warps over 64)

    const int m0 = blockIdx.y * BM;
    const int n0 = blockIdx.x * BN;
    const int z  = blockIdx.z;

    const float* Ag;
    const float* Bg;
    if (MODE == 3) {
        Ag = Abase + ((size_t)z * TLEN + m0) * HD;
        Bg = Bbase + ((size_t)z * SLEN + n0) * HD;
    } else if (MODE == 4) {
        Ag = Abase + ((size_t)z * TLEN + m0) * SLEN;
        Bg = Bbase + (size_t)z * HD * SLEN;
    } else {
        Ag = Abase + (size_t)m0 * lda;
        Bg = Bbase + (size_t)n0 * ldb;
    }

    if (MODE <= 2) {
        if (tid < 64) ((float*)(sm + SM_BIAS))[tid] = bias[n0 + tid];
    }

    float d[2][4][4] = {};   // [mt][nt][reg]

    for (int k0 = 0; k0 < Ktot; k0 += BK) {
        // ---- load + split A tile: 128 x 32 (4 float4 per thread) ----
        #pragma unroll
        for (int i = 0; i < 4; i++) {
            const int idx = tid + i * 256;
            const int r = idx >> 3, c4 = (idx & 7) << 2;
            const float4 v = *(const float4*)(Ag + (size_t)r * lda + k0 + c4);
            uint32_t h0, l0, h1, l1;
            split2(v.x, v.y, h0, l0);
            split2(v.z, v.w, h1, l1);
            const int off = r * ROWB + c4 * 2;
            *(uint2*)(sm + SM_AH + off) = make_uint2(h0, h1);
            *(uint2*)(sm + SM_AL + off) = make_uint2(l0, l1);
        }
        // ---- load + split B tile: 64 x 32 (2 float4 per thread) ----
        #pragma unroll
        for (int i = 0; i < 2; i++) {
            const int idx = tid + i * 256;
            const int r = idx >> 3, c4 = (idx & 7) << 2;
            const float4 v = *(const float4*)(Bg + (size_t)r * ldb + k0 + c4);
            uint32_t h0, l0, h1, l1;
            split2(v.x, v.y, h0, l0);
            split2(v.z, v.w, h1, l1);
            const int off = r * ROWB + c4 * 2;
            *(uint2*)(sm + SM_BH + off) = make_uint2(h0, h1);
            *(uint2*)(sm + SM_BL + off) = make_uint2(l0, l1);
        }
        __syncthreads();

        #pragma unroll
        for (int ks = 0; ks < 2; ks++) {
            // A fragments (hi & lo)
            uint4 ah[2], al[2];
            {
                const int arow_g = ((lane >> 3) & 1) * 8 + (lane & 7);
                const int akb = ks * 32 + (lane >> 4) * 16;
                #pragma unroll
                for (int mt = 0; mt < 2; mt++) {
                    const int off = (wm + mt * 16 + arow_g) * ROWB + akb;
                    ah[mt] = ldm_x4(smb + SM_AH + off);
                    al[mt] = ldm_x4(smb + SM_AL + off);
                }
            }
            // B fragments (hi & lo): each x4 covers two n8 tiles
            uint4 bh[2], bl[2];
            {
                const int brow_g = (lane >> 4) * 8 + (lane & 7);
                const int bkb = ks * 32 + ((lane >> 3) & 1) * 16;
                #pragma unroll
                for (int np = 0; np < 2; np++) {
                    const int off = (wn + np * 16 + brow_g) * ROWB + bkb;
                    bh[np] = ldm_x4(smb + SM_BH + off);
                    bl[np] = ldm_x4(smb + SM_BL + off);
                }
            }
            #pragma unroll
            for (int mt = 0; mt < 2; mt++) {
                #pragma unroll
                for (int nt = 0; nt < 4; nt++) {
                    const uint4& BH = bh[nt >> 1];
                    const uint4& BL = bl[nt >> 1];
                    const uint32_t bh0 = (nt & 1) ? BH.z : BH.x;
                    const uint32_t bh1 = (nt & 1) ? BH.w : BH.y;
                    const uint32_t bl0 = (nt & 1) ? BL.z : BL.x;
                    const uint32_t bl1 = (nt & 1) ? BL.w : BL.y;
                    mma16816(d[mt][nt], ah[mt], bh0, bh1);   // Ah*Bh
                    mma16816(d[mt][nt], ah[mt], bl0, bl1);   // Ah*Bl
                    mma16816(d[mt][nt], al[mt], bh0, bh1);   // Al*Bh
                }
            }
        }
        __syncthreads();
    }

    // ---- stage accumulators to smem (row-major [128][STG_LD]) ----
    float* stg = (float*)(sm + SM_STAGE);
    #pragma unroll
    for (int mt = 0; mt < 2; mt++) {
        #pragma unroll
        for (int nt = 0; nt < 4; nt++) {
            const int r = wm + mt * 16 + (lane >> 2);
            const int c = wn + nt * 8 + (lane & 3) * 2;
            stg[r * STG_LD + c]           = d[mt][nt][0];
            stg[r * STG_LD + c + 1]       = d[mt][nt][1];
            stg[(r + 8) * STG_LD + c]     = d[mt][nt][2];
            stg[(r + 8) * STG_LD + c + 1] = d[mt][nt][3];
        }
    }
    __syncthreads();

    const float* sBias = (const float*)(sm + SM_BIAS);

    if (MODE == 0 || MODE == 1) {
        // 128 rows x 16 float4 = 2048 slots, 8 per thread
        #pragma unroll
        for (int i = 0; i < 8; i++) {
            const int idx = tid + i * 256;
            const int r = idx >> 4, c = (idx & 15) << 2;
            float4 v;
            v.x = (stg[r * STG_LD + c]     + sBias[c])     * scale;
            v.y = (stg[r * STG_LD + c + 1] + sBias[c + 1]) * scale;
            v.z = (stg[r * STG_LD + c + 2] + sBias[c + 2]) * scale;
            v.w = (stg[r * STG_LD + c + 3] + sBias[c + 3]) * scale;
            if (MODE == 0) {
                *(float4*)(out + (size_t)(m0 + r) * EDIM + n0 + c) = v;
            } else {
                const int row = m0 + r;
                const int t = row >> 1, b = row & 1;
                const int h = n0 >> 6;
                *(float4*)(out + ((size_t)(b * NH + h) * TLEN + t) * HD + c) = v;
            }
        }
    } else if (MODE == 2) {
        // Vt: column writer. thread (c = tid>>1, b = tid&1), writes 64 s-values
        if (tid < 128) {
            const int c = tid >> 1, b = tid & 1;
            const int h = n0 >> 6;
            const float vb = sBias[c];
            float* o = out + ((size_t)((b * NH + h) * HD + c)) * SLEN + (m0 >> 1);
            #pragma unroll
            for (int j = 0; j < 64; j += 4) {
                float4 v;
                v.x = (stg[(2 * (j + 0) + b) * STG_LD + c] + vb) * scale;
                v.y = (stg[(2 * (j + 1) + b) * STG_LD + c] + vb) * scale;
                v.z = (stg[(2 * (j + 2) + b) * STG_LD + c] + vb) * scale;
                v.w = (stg[(2 * (j + 3) + b) * STG_LD + c] + vb) * scale;
                *(float4*)(o + j) = v;
            }
        }
    } else if (MODE == 3) {
        #pragma unroll
        for (int i = 0; i < 8; i++) {
            const int idx = tid + i * 256;
            const int r = idx >> 4, c = (idx & 15) << 2;
            float4 v = make_float4(stg[r * STG_LD + c], stg[r * STG_LD + c + 1],
                                   stg[r * STG_LD + c + 2], stg[r * STG_LD + c + 3]);
            *(float4*)(out + ((size_t)z * TLEN + m0 + r) * SLEN + n0 + c) = v;
        }
    } else { // MODE 4
        const int bb = z >> 4, hh = z & 15;
        #pragma unroll
        for (int i = 0; i < 8; i++) {
            const int idx = tid + i * 256;
            const int r = idx >> 4, c = (idx & 15) << 2;
            float4 v = make_float4(stg[r * STG_LD + c], stg[r * STG_LD + c + 1],
                                   stg[r * STG_LD + c + 2], stg[r * STG_LD + c + 3]);
            *(float4*)(out + ((size_t)(m0 + r) * BSZ + bb) * EDIM + hh * HD + c) = v;
        }
    }
}

// ============================================================================
// Row softmax with mask + dynamic threshold drop (validated in round 1)
// ============================================================================
__global__ __launch_bounds__(256)
void softmax_kernel(const float* __restrict__ Sin, const int* __restrict__ mask,
                    float* __restrict__ P)
{
    const int row = blockIdx.x;
    const int t = row & (TLEN - 1);
    const int tid = threadIdx.x;
    const float* sr = Sin + (size_t)row * SLEN;

    float v[8];
    float m = -INFINITY;
    #pragma unroll
    for (int i = 0; i < 8; i++) {
        const int s = tid + i * 256;
        float x = sr[s];
        if (mask[(size_t)t * SLEN + s] == 0) x = -INFINITY;
        v[i] = x;
        m = fmaxf(m, x);
    }
    __shared__ float red[256];
    red[tid] = m;
    __syncthreads();
    #pragma unroll
    for (int st = 128; st > 0; st >>= 1) {
        if (tid < st) red[tid] = fmaxf(red[tid], red[tid + st]);
        __syncthreads();
    }
    m = red[0];
    __syncthreads();

    const float thr = m - DTHRESH;
    float sum = 0.f;
    #pragma unroll
    for (int i = 0; i < 8; i++) {
        float e = (v[i] < thr) ? 0.0f : __expf(v[i] - m);
        v[i] = e;
        sum += e;
    }
    red[tid] = sum;
    __syncthreads();
    #pragma unroll
    for (int st = 128; st > 0; st >>= 1) {
        if (tid < st) red[tid] += red[tid + st];
        __syncthreads();
    }
    const float inv = 1.0f / red[0];
    float* pr = P + (size_t)row * SLEN;
    #pragma unroll
    for (int i = 0; i < 8; i++)
        pr[tid + i * 256] = v[i] * inv;
}

// ============================================================================
// Launch
// ============================================================================
extern "C" void kernel_launch(void* const* d_in, const int* in_sizes, int n_in,
                              void* d_out, int out_size)
{
    const float* query = (const float*)d_in[0];
    const float* key   = (const float*)d_in[1];
    const float* value = (const float*)d_in[2];
    const int*   mask  = (const int*)  d_in[3];
    const float* Wq    = (const float*)d_in[4];
    const float* bq    = (const float*)d_in[5];
    const float* Wk    = (const float*)d_in[6];
    const float* bk    = (const float*)d_in[7];
    const float* Wv    = (const float*)d_in[8];
    const float* bv    = (const float*)d_in[9];
    const float* Wo    = (const float*)d_in[10];
    const float* bo    = (const float*)d_in[11];
    float* out = (float*)d_out;

    float *pQ, *pK, *pVt, *pS, *pA;
    cudaGetSymbolAddress((void**)&pQ,  g_Q);
    cudaGetSymbolAddress((void**)&pK,  g_K);
    cudaGetSymbolAddress((void**)&pVt, g_Vt);
    cudaGetSymbolAddress((void**)&pS,  g_S);
    cudaGetSymbolAddress((void**)&pA,  g_A);

    const bool export_weights = ((size_t)out_size >= ATTN_ELEMS + WEIGHT_ELEMS);
    float* weights = export_weights ? (out + ATTN_ELEMS) : pS;

    static bool smem_set = false;
    if (!smem_set) {
        cudaFuncSetAttribute(mma_gemm<0>, cudaFuncAttributeMaxDynamicSharedMemorySize, SMEM_BYTES);
        cudaFuncSetAttribute(mma_gemm<1>, cudaFuncAttributeMaxDynamicSharedMemorySize, SMEM_BYTES);
        cudaFuncSetAttribute(mma_gemm<2>, cudaFuncAttributeMaxDynamicSharedMemorySize, SMEM_BYTES);
        cudaFuncSetAttribute(mma_gemm<3>, cudaFuncAttributeMaxDynamicSharedMemorySize, SMEM_BYTES);
        cudaFuncSetAttribute(mma_gemm<4>, cudaFuncAttributeMaxDynamicSharedMemorySize, SMEM_BYTES);
        smem_set = true;
    }

    dim3 gproj(EDIM / BN, MTOK / BM, 1);       // 16 x 32
    mma_gemm<1><<<gproj, 256, SMEM_BYTES>>>(query, Wq, bq, pQ,  SCALING, EDIM, EDIM, EDIM);
    mma_gemm<1><<<gproj, 256, SMEM_BYTES>>>(key,   Wk, bk, pK,  1.0f,    EDIM, EDIM, EDIM);
    mma_gemm<2><<<gproj, 256, SMEM_BYTES>>>(value, Wv, bv, pVt, 1.0f,    EDIM, EDIM, EDIM);

    dim3 gqk(SLEN / BN, TLEN / BM, NZ);        // 32 x 16 x 32
    mma_gemm<3><<<gqk, 256, SMEM_BYTES>>>(pQ, pK, nullptr, pS, 1.0f, HD, HD, HD);

    softmax_kernel<<<NZ * TLEN, 256>>>(pS, mask, weights);

    dim3 gpv(1, TLEN / BM, NZ);                // 1 x 16 x 32
    mma_gemm<4><<<gpv, 256, SMEM_BYTES>>>(weights, pVt, nullptr, pA, 1.0f, SLEN, SLEN, SLEN);

    mma_gemm<0><<<gproj, 256, SMEM_BYTES>>>(pA, Wo, bo, out, 1.0f, EDIM, EDIM, EDIM);
}

// round 14
// speedup vs baseline: 2.0925x; 1.1734x over previous
#include <cuda_runtime.h>
#include <cuda_bf16.h>
#include <math.h>
#include <cstdint>

// ---------------- problem constants ----------------
#define EDIM 1024
#define NH   16
#define HD   64
#define TLEN 2048
#define SLEN 2048
#define BSZ  2
#define NZ   (BSZ*NH)    // 32
#define MTOK (TLEN*BSZ)  // 4096
#define SCALING 0.125f
#define DTHRESH 3.8918202981106265f

#define ATTN_ELEMS ((size_t)TLEN*BSZ*EDIM)
#define WEIGHT_ELEMS ((size_t)NZ*TLEN*SLEN)

// ---------------- scratch ----------------
static __device__ float g_Q[(size_t)NZ*TLEN*HD];      // [z][t][64]
static __device__ float g_K[(size_t)NZ*SLEN*HD];      // [z][s][64]
static __device__ float g_Vt[(size_t)NZ*HD*SLEN];     // [z][64][s]
static __device__ float g_S[(size_t)NZ*TLEN*SLEN];    // scores / probs
static __device__ float g_A[(size_t)MTOK*EDIM];       // attn pre-out-proj [token][f]

// ---------------- tile config ----------------
#define BM 128
#define BN 64
#define BK 32
#define ROWB 80            // smem row stride bytes (32 bf16 = 64B + 16 pad)

// per-stage smem sublayout (bytes)
#define ST_AH 0            // 128*80 = 10240
#define ST_AL 10240
#define ST_BH 20480        // 64*80 = 5120
#define ST_BL 25600
#define STAGE_B 30720      // one stage
#define SM_BIAS (2*STAGE_B)            // 61440
#define SMEM_BYTES (2*STAGE_B + 256)   // 61696
#define SM_STAGE 0                     // epilogue overlay (128*68*4 = 34816 < 61440)
#define STG_LD 68

__device__ __forceinline__ uint32_t smem_u32(const void* p) {
    uint32_t a;
    asm("{ .reg .u64 t; cvta.to.shared.u64 t, %1; cvt.u32.u64 %0, t; }" : "=r"(a) : "l"(p));
    return a;
}

__device__ __forceinline__ uint4 ldm_x4(uint32_t addr) {
    uint4 r;
    asm volatile("ldmatrix.sync.aligned.m8n8.x4.shared.b16 {%0,%1,%2,%3}, [%4];"
                 : "=r"(r.x), "=r"(r.y), "=r"(r.z), "=r"(r.w) : "r"(addr));
    return r;
}

__device__ __forceinline__ void mma16816(float* d, const uint4& a, uint32_t b0, uint32_t b1) {
    asm volatile("mma.sync.aligned.m16n8k16.row.col.f32.bf16.bf16.f32 "
                 "{%0,%1,%2,%3}, {%4,%5,%6,%7}, {%8,%9}, {%0,%1,%2,%3};"
                 : "+f"(d[0]), "+f"(d[1]), "+f"(d[2]), "+f"(d[3])
                 : "r"(a.x), "r"(a.y), "r"(a.z), "r"(a.w), "r"(b0), "r"(b1));
}

__device__ __forceinline__ void split2(float x, float y, uint32_t& hi, uint32_t& lo) {
    __nv_bfloat16 hx = __float2bfloat16(x);
    __nv_bfloat16 hy = __float2bfloat16(y);
    __nv_bfloat16 lx = __float2bfloat16(x - __bfloat162float(hx));
    __nv_bfloat16 ly = __float2bfloat16(y - __bfloat162float(hy));
    hi = (uint32_t)__bfloat16_as_ushort(hx) | ((uint32_t)__bfloat16_as_ushort(hy) << 16);
    lo = (uint32_t)__bfloat16_as_ushort(lx) | ((uint32_t)__bfloat16_as_ushort(ly) << 16);
}

// ============================================================================
// Unified GEMM:  C[BMxBN] = A[BM x K] * B[BN x K]^T   (both K-contiguous)
// MODE 0: proj -> plain [token][1024]
// MODE 1: proj -> per-head q/k  [z][t][64]
// MODE 2: proj -> Vt            [z][64][s]
// MODE 3: QK   -> scores        [z][t][s]
// MODE 4: PV   -> attn          [token][1024] (n0 = 0, N=64 per z)
// bf16 2-way split (3 products), double-buffered smem, register prefetch.
// ============================================================================
template <int MODE>
__global__ __launch_bounds__(256, 2)
void mma_gemm(const float* __restrict__ Abase, const float* __restrict__ Bbase,
              const float* __restrict__ bias, float* __restrict__ out,
              float scale, int lda, int ldb, int Ktot)
{
    extern __shared__ char sm[];
    const uint32_t smb = smem_u32(sm);
    const int tid = threadIdx.x;
    const int lane = tid & 31, wid = tid >> 5;
    const int wm = (wid & 3) * 32;
    const int wn = (wid >> 2) * 32;

    const int m0 = blockIdx.y * BM;
    const int n0 = blockIdx.x * BN;
    const int z  = blockIdx.z;

    const float* Ag;
    const float* Bg;
    if (MODE == 3) {
        Ag = Abase + ((size_t)z * TLEN + m0) * HD;
        Bg = Bbase + ((size_t)z * SLEN + n0) * HD;
    } else if (MODE == 4) {
        Ag = Abase + ((size_t)z * TLEN + m0) * SLEN;
        Bg = Bbase + (size_t)z * HD * SLEN;
    } else {
        Ag = Abase + (size_t)m0 * lda;
        Bg = Bbase + (size_t)n0 * ldb;
    }

    if (MODE <= 2) {
        if (tid < 64) ((float*)(sm + SM_BIAS))[tid] = bias[n0 + tid];
    }

    float d[2][4][4] = {};
    float4 pa[4], pb[2];

    const int nk = Ktot / BK;

    // ---- prologue: load + store chunk 0 ----
    #pragma unroll
    for (int i = 0; i < 4; i++) {
        const int idx = tid + i * 256;
        const int r = idx >> 3, c4 = (idx & 7) << 2;
        pa[i] = *(const float4*)(Ag + (size_t)r * lda + c4);
    }
    #pragma unroll
    for (int i = 0; i < 2; i++) {
        const int idx = tid + i * 256;
        const int r = idx >> 3, c4 = (idx & 7) << 2;
        pb[i] = *(const float4*)(Bg + (size_t)r * ldb + c4);
    }
    {
        char* st = sm;   // stage 0
        #pragma unroll
        for (int i = 0; i < 4; i++) {
            const int idx = tid + i * 256;
            const int r = idx >> 3, c4 = (idx & 7) << 2;
            uint32_t h0, l0, h1, l1;
            split2(pa[i].x, pa[i].y, h0, l0);
            split2(pa[i].z, pa[i].w, h1, l1);
            const int off = r * ROWB + c4 * 2;
            *(uint2*)(st + ST_AH + off) = make_uint2(h0, h1);
            *(uint2*)(st + ST_AL + off) = make_uint2(l0, l1);
        }
        #pragma unroll
        for (int i = 0; i < 2; i++) {
            const int idx = tid + i * 256;
            const int r = idx >> 3, c4 = (idx & 7) << 2;
            uint32_t h0, l0, h1, l1;
            split2(pb[i].x, pb[i].y, h0, l0);
            split2(pb[i].z, pb[i].w, h1, l1);
            const int off = r * ROWB + c4 * 2;
            *(uint2*)(st + ST_BH + off) = make_uint2(h0, h1);
            *(uint2*)(st + ST_BL + off) = make_uint2(l0, l1);
        }
    }
    __syncthreads();

    int cur = 0;
    for (int kc = 0; kc < nk; kc++) {
        const bool more = (kc + 1 < nk);
        // ---- prefetch next chunk into registers (overlaps with mma below) ----
        if (more) {
            const int k0 = (kc + 1) * BK;
            #pragma unroll
            for (int i = 0; i < 4; i++) {
                const int idx = tid + i * 256;
                const int r = idx >> 3, c4 = (idx & 7) << 2;
                pa[i] = *(const float4*)(Ag + (size_t)r * lda + k0 + c4);
            }
            #pragma unroll
            for (int i = 0; i < 2; i++) {
                const int idx = tid + i * 256;
                const int r = idx >> 3, c4 = (idx & 7) << 2;
                pb[i] = *(const float4*)(Bg + (size_t)r * ldb + k0 + c4);
            }
        }

        // ---- mma on current stage ----
        const uint32_t sb = smb + cur * STAGE_B;
        #pragma unroll
        for (int ks = 0; ks < 2; ks++) {
            uint4 ah[2], al[2];
            {
                const int arow_g = ((lane >> 3) & 1) * 8 + (lane & 7);
                const int akb = ks * 32 + (lane >> 4) * 16;
                #pragma unroll
                for (int mt = 0; mt < 2; mt++) {
                    const int off = (wm + mt * 16 + arow_g) * ROWB + akb;
                    ah[mt] = ldm_x4(sb + ST_AH + off);
                    al[mt] = ldm_x4(sb + ST_AL + off);
                }
            }
            uint4 bh[2], bl[2];
            {
                const int brow_g = (lane >> 4) * 8 + (lane & 7);
                const int bkb = ks * 32 + ((lane >> 3) & 1) * 16;
                #pragma unroll
                for (int np = 0; np < 2; np++) {
                    const int off = (wn + np * 16 + brow_g) * ROWB + bkb;
                    bh[np] = ldm_x4(sb + ST_BH + off);
                    bl[np] = ldm_x4(sb + ST_BL + off);
                }
            }
            #pragma unroll
            for (int mt = 0; mt < 2; mt++) {
                #pragma unroll
                for (int nt = 0; nt < 4; nt++) {
                    const uint4& BH = bh[nt >> 1];
                    const uint4& BL = bl[nt >> 1];
                    const uint32_t bh0 = (nt & 1) ? BH.z : BH.x;
                    const uint32_t bh1 = (nt & 1) ? BH.w : BH.y;
                    const uint32_t bl0 = (nt & 1) ? BL.z : BL.x;
                    const uint32_t bl1 = (nt & 1) ? BL.w : BL.y;
                    mma16816(d[mt][nt], ah[mt], bh0, bh1);
                    mma16816(d[mt][nt], ah[mt], bl0, bl1);
                    mma16816(d[mt][nt], al[mt], bh0, bh1);
                }
            }
        }

        // ---- store prefetched chunk into alternate stage ----
        if (more) {
            char* st = sm + (cur ^ 1) * STAGE_B;
            #pragma unroll
            for (int i = 0; i < 4; i++) {
                const int idx = tid + i * 256;
                const int r = idx >> 3, c4 = (idx & 7) << 2;
                uint32_t h0, l0, h1, l1;
                split2(pa[i].x, pa[i].y, h0, l0);
                split2(pa[i].z, pa[i].w, h1, l1);
                const int off = r * ROWB + c4 * 2;
                *(uint2*)(st + ST_AH + off) = make_uint2(h0, h1);
                *(uint2*)(st + ST_AL + off) = make_uint2(l0, l1);
            }
            #pragma unroll
            for (int i = 0; i < 2; i++) {
                const int idx = tid + i * 256;
                const int r = idx >> 3, c4 = (idx & 7) << 2;
                uint32_t h0, l0, h1, l1;
                split2(pb[i].x, pb[i].y, h0, l0);
                split2(pb[i].z, pb[i].w, h1, l1);
                const int off = r * ROWB + c4 * 2;
                *(uint2*)(st + ST_BH + off) = make_uint2(h0, h1);
                *(uint2*)(st + ST_BL + off) = make_uint2(l0, l1);
            }
        }
        __syncthreads();
        cur ^= 1;
    }

    // ---- stage accumulators to smem ----
    float* stg = (float*)(sm + SM_STAGE);
    #pragma unroll
    for (int mt = 0; mt < 2; mt++) {
        #pragma unroll
        for (int nt = 0; nt < 4; nt++) {
            const int r = wm + mt * 16 + (lane >> 2);
            const int c = wn + nt * 8 + (lane & 3) * 2;
            stg[r * STG_LD + c]           = d[mt][nt][0];
            stg[r * STG_LD + c + 1]       = d[mt][nt][1];
            stg[(r + 8) * STG_LD + c]     = d[mt][nt][2];
            stg[(r + 8) * STG_LD + c + 1] = d[mt][nt][3];
        }
    }
    __syncthreads();

    const float* sBias = (const float*)(sm + SM_BIAS);

    if (MODE == 0 || MODE == 1) {
        #pragma unroll
        for (int i = 0; i < 8; i++) {
            const int idx = tid + i * 256;
            const int r = idx >> 4, c = (idx & 15) << 2;
            float4 v;
            v.x = (stg[r * STG_LD + c]     + sBias[c])     * scale;
            v.y = (stg[r * STG_LD + c + 1] + sBias[c + 1]) * scale;
            v.z = (stg[r * STG_LD + c + 2] + sBias[c + 2]) * scale;
            v.w = (stg[r * STG_LD + c + 3] + sBias[c + 3]) * scale;
            if (MODE == 0) {
                *(float4*)(out + (size_t)(m0 + r) * EDIM + n0 + c) = v;
            } else {
                const int row = m0 + r;
                const int t = row >> 1, b = row & 1;
                const int h = n0 >> 6;
                *(float4*)(out + ((size_t)(b * NH + h) * TLEN + t) * HD + c) = v;
            }
        }
    } else if (MODE == 2) {
        if (tid < 128) {
            const int c = tid >> 1, b = tid & 1;
            const int h = n0 >> 6;
            const float vb = sBias[c];
            float* o = out + ((size_t)((b * NH + h) * HD + c)) * SLEN + (m0 >> 1);
            #pragma unroll
            for (int j = 0; j < 64; j += 4) {
                float4 v;
                v.x = (stg[(2 * (j + 0) + b) * STG_LD + c] + vb) * scale;
                v.y = (stg[(2 * (j + 1) + b) * STG_LD + c] + vb) * scale;
                v.z = (stg[(2 * (j + 2) + b) * STG_LD + c] + vb) * scale;
                v.w = (stg[(2 * (j + 3) + b) * STG_LD + c] + vb) * scale;
                *(float4*)(o + j) = v;
            }
        }
    } else if (MODE == 3) {
        #pragma unroll
        for (int i = 0; i < 8; i++) {
            const int idx = tid + i * 256;
            const int r = idx >> 4, c = (idx & 15) << 2;
            float4 v = make_float4(stg[r * STG_LD + c], stg[r * STG_LD + c + 1],
                                   stg[r * STG_LD + c + 2], stg[r * STG_LD + c + 3]);
            *(float4*)(out + ((size_t)z * TLEN + m0 + r) * SLEN + n0 + c) = v;
        }
    } else { // MODE 4
        const int bb = z >> 4, hh = z & 15;
        #pragma unroll
        for (int i = 0; i < 8; i++) {
            const int idx = tid + i * 256;
            const int r = idx >> 4, c = (idx & 15) << 2;
            float4 v = make_float4(stg[r * STG_LD + c], stg[r * STG_LD + c + 1],
                                   stg[r * STG_LD + c + 2], stg[r * STG_LD + c + 3]);
            *(float4*)(out + ((size_t)(m0 + r) * BSZ + bb) * EDIM + hh * HD + c) = v;
        }
    }
}

// ============================================================================
// Row softmax: float4 loads, warp-shuffle reductions
// ============================================================================
__global__ __launch_bounds__(256)
void softmax_kernel(const float* __restrict__ Sin, const int* __restrict__ mask,
                    float* __restrict__ P)
{
    const int row = blockIdx.x;
    const int t = row & (TLEN - 1);
    const int tid = threadIdx.x;
    const int lane = tid & 31, wid = tid >> 5;
    const float4* sr = (const float4*)(Sin + (size_t)row * SLEN);
    const int4*   mr = (const int4*)(mask + (size_t)t * SLEN);

    float4 v[2];
    float m = -INFINITY;
    #pragma unroll
    for (int i = 0; i < 2; i++) {
        const int q = tid + i * 256;
        float4 x = sr[q];
        int4 mk = mr[q];
        if (mk.x == 0) x.x = -INFINITY;
        if (mk.y == 0) x.y = -INFINITY;
        if (mk.z == 0) x.z = -INFINITY;
        if (mk.w == 0) x.w = -INFINITY;
        v[i] = x;
        m = fmaxf(m, fmaxf(fmaxf(x.x, x.y), fmaxf(x.z, x.w)));
    }

    __shared__ float red[8];
    #pragma unroll
    for (int off = 16; off > 0; off >>= 1)
        m = fmaxf(m, __shfl_xor_sync(0xFFFFFFFFu, m, off));
    if (lane == 0) red[wid] = m;
    __syncthreads();
    m = red[0];
    #pragma unroll
    for (int i = 1; i < 8; i++) m = fmaxf(m, red[i]);
    __syncthreads();

    const float thr = m - DTHRESH;
    float sum = 0.f;
    #pragma unroll
    for (int i = 0; i < 2; i++) {
        float4 x = v[i];
        x.x = (x.x < thr) ? 0.0f : __expf(x.x - m);
        x.y = (x.y < thr) ? 0.0f : __expf(x.y - m);
        x.z = (x.z < thr) ? 0.0f : __expf(x.z - m);
        x.w = (x.w < thr) ? 0.0f : __expf(x.w - m);
        v[i] = x;
        sum += x.x + x.y + x.z + x.w;
    }
    #pragma unroll
    for (int off = 16; off > 0; off >>= 1)
        sum += __shfl_xor_sync(0xFFFFFFFFu, sum, off);
    if (lane == 0) red[wid] = sum;
    __syncthreads();
    sum = red[0];
    #pragma unroll
    for (int i = 1; i < 8; i++) sum += red[i];
    const float inv = 1.0f / sum;

    float4* pr = (float4*)(P + (size_t)row * SLEN);
    #pragma unroll
    for (int i = 0; i < 2; i++) {
        float4 x = v[i];
        x.x *= inv; x.y *= inv; x.z *= inv; x.w *= inv;
        pr[tid + i * 256] = x;
    }
}

// ============================================================================
// Launch
// ============================================================================
extern "C" void kernel_launch(void* const* d_in, const int* in_sizes, int n_in,
                              void* d_out, int out_size)
{
    const float* query = (const float*)d_in[0];
    const float* key   = (const float*)d_in[1];
    const float* value = (const float*)d_in[2];
    const int*   mask  = (const int*)  d_in[3];
    const float* Wq    = (const float*)d_in[4];
    const float* bq    = (const float*)d_in[5];
    const float* Wk    = (const float*)d_in[6];
    const float* bk    = (const float*)d_in[7];
    const float* Wv    = (const float*)d_in[8];
    const float* bv    = (const float*)d_in[9];
    const float* Wo    = (const float*)d_in[10];
    const float* bo    = (const float*)d_in[11];
    float* out = (float*)d_out;

    float *pQ, *pK, *pVt, *pS, *pA;
    cudaGetSymbolAddress((void**)&pQ,  g_Q);
    cudaGetSymbolAddress((void**)&pK,  g_K);
    cudaGetSymbolAddress((void**)&pVt, g_Vt);
    cudaGetSymbolAddress((void**)&pS,  g_S);
    cudaGetSymbolAddress((void**)&pA,  g_A);

    const bool export_weights = ((size_t)out_size >= ATTN_ELEMS + WEIGHT_ELEMS);
    float* weights = export_weights ? (out + ATTN_ELEMS) : pS;

    static bool smem_set = false;
    if (!smem_set) {
        cudaFuncSetAttribute(mma_gemm<0>, cudaFuncAttributeMaxDynamicSharedMemorySize, SMEM_BYTES);
        cudaFuncSetAttribute(mma_gemm<1>, cudaFuncAttributeMaxDynamicSharedMemorySize, SMEM_BYTES);
        cudaFuncSetAttribute(mma_gemm<2>, cudaFuncAttributeMaxDynamicSharedMemorySize, SMEM_BYTES);
        cudaFuncSetAttribute(mma_gemm<3>, cudaFuncAttributeMaxDynamicSharedMemorySize, SMEM_BYTES);
        cudaFuncSetAttribute(mma_gemm<4>, cudaFuncAttributeMaxDynamicSharedMemorySize, SMEM_BYTES);
        smem_set = true;
    }

    dim3 gproj(EDIM / BN, MTOK / BM, 1);       // 16 x 32
    mma_gemm<1><<<gproj, 256, SMEM_BYTES>>>(query, Wq, bq, pQ,  SCALING, EDIM, EDIM, EDIM);
    mma_gemm<1><<<gproj, 256, SMEM_BYTES>>>(key,   Wk, bk, pK,  1.0f,    EDIM, EDIM, EDIM);
    mma_gemm<2><<<gproj, 256, SMEM_BYTES>>>(value, Wv, bv, pVt, 1.0f,    EDIM, EDIM, EDIM);

    dim3 gqk(SLEN / BN, TLEN / BM, NZ);        // 32 x 16 x 32
    mma_gemm<3><<<gqk, 256, SMEM_BYTES>>>(pQ, pK, nullptr, pS, 1.0f, HD, HD, HD);

    softmax_kernel<<<NZ * TLEN, 256>>>(pS, mask, weights);

    dim3 gpv(1, TLEN / BM, NZ);                // 1 x 16 x 32
    mma_gemm<4><<<gpv, 256, SMEM_BYTES>>>(weights, pVt, nullptr, pA, 1.0f, SLEN, SLEN, SLEN);

    mma_gemm<0><<<gproj, 256, SMEM_BYTES>>>(pA, Wo, bo, out, 1.0f, EDIM, EDIM, EDIM);
}